// round 9
// baseline (speedup 1.0000x reference)
#include <cuda_runtime.h>
#include <cuda_bf16.h>
#include <math.h>
#include <stdint.h>

#define N_NODES 4096
#define F 256
#define H 4
#define HD 64
#define WPR (N_NODES / 32)
#define MAXN 256

typedef __nv_bfloat16 bf16;

// ---- scratch (static device arrays; no allocations allowed) ----
__device__ float g_Q[N_NODES * F];
__device__ float g_K[N_NODES * F];
__device__ float g_V[N_NODES * F];
__device__ unsigned g_adj[N_NODES * WPR];
__device__ bf16 g_xh[N_NODES * F];
__device__ bf16 g_xl[N_NODES * F];
__device__ bf16 g_Wh[3 * F * F];
__device__ bf16 g_Wl[3 * F * F];

// ---------------------------------------------------------------------------
// PTX helpers
// ---------------------------------------------------------------------------
__device__ __forceinline__ void cp16(void* dst, const void* src) {
    unsigned d = (unsigned)__cvta_generic_to_shared(dst);
    asm volatile("cp.async.cg.shared.global [%0], [%1], 16;" :: "r"(d), "l"(src));
}
__device__ __forceinline__ void ldm4(unsigned* r, const void* p) {
    unsigned a = (unsigned)__cvta_generic_to_shared(p);
    asm volatile("ldmatrix.sync.aligned.m8n8.x4.shared.b16 {%0,%1,%2,%3}, [%4];"
                 : "=r"(r[0]), "=r"(r[1]), "=r"(r[2]), "=r"(r[3]) : "r"(a));
}
__device__ __forceinline__ void mma16816(float* c, const unsigned* a, const unsigned* b) {
    asm volatile(
        "mma.sync.aligned.m16n8k16.row.col.f32.bf16.bf16.f32 "
        "{%0,%1,%2,%3}, {%4,%5,%6,%7}, {%8,%9}, {%0,%1,%2,%3};"
        : "+f"(c[0]), "+f"(c[1]), "+f"(c[2]), "+f"(c[3])
        : "r"(a[0]), "r"(a[1]), "r"(a[2]), "r"(a[3]), "r"(b[0]), "r"(b[1]));
}
// streaming (evict-first) stores: keep 268MB write-once traffic out of L2's way
__device__ __forceinline__ void stg_cs_zero4(float* p) {
    asm volatile("st.global.cs.v4.f32 [%0], {%1, %1, %1, %1};"
                 :: "l"(p), "f"(0.0f) : "memory");
}
__device__ __forceinline__ void stg_cs_f32(float* p, float v) {
    asm volatile("st.global.cs.f32 [%0], %1;" :: "l"(p), "f"(v) : "memory");
}

// ---------------------------------------------------------------------------
// Prep: bf16 hi/lo split of x and [Wq;Wk;Wv] + adjacency bitmap clear (fused)
// ---------------------------------------------------------------------------
#define NX (N_NODES * F)
#define NW (3 * F * F)
#define NADJ (N_NODES * WPR)
__global__ void convert_kernel(const float* __restrict__ x,
                               const float* __restrict__ Wq,
                               const float* __restrict__ Wk,
                               const float* __restrict__ Wv) {
    int i = blockIdx.x * 256 + threadIdx.x;
    float v; bf16 *dh, *dl; int di;
    if (i < NX) { v = x[i]; dh = g_xh; dl = g_xl; di = i; }
    else if (i < NX + NW) {
        int j = i - NX;
        int mat = j >> 16; int e = j & 65535;
        v = (mat == 0 ? Wq : mat == 1 ? Wk : Wv)[e];
        dh = g_Wh; dl = g_Wl; di = j;
    } else {
        int j = i - NX - NW;
        if (j < NADJ) g_adj[j] = 0u;
        return;
    }
    bf16 h = __float2bfloat16(v);
    dh[di] = h;
    dl[di] = __float2bfloat16(v - __bfloat162float(h));
}

__global__ void scatter_edges_kernel(const int* __restrict__ ei, int E) {
    int i = blockIdx.x * blockDim.x + threadIdx.x;
    if (i >= E) return;
    int s = ei[i];
    int d = ei[E + i];
    atomicOr(&g_adj[s * WPR + (d >> 5)], 1u << (d & 31));
}

// ---------------------------------------------------------------------------
// Tensor-core QKV GEMM (bf16 hi/lo, 3-term) + head-0 attn zeroing (st.cs).
// BM=64 BN=128, grid (64,6)=384 blocks, 256 thr = 8 warps, warp tile 16x64.
// 3-stage cp.async pipeline, one __syncthreads per k-step, 48B-stride smem.
// ---------------------------------------------------------------------------
#define SA_BYTES (3 * 2 * 64 * 24 * 2)    // 18432
#define SB_BYTES (3 * 2 * 128 * 24 * 2)   // 36864
#define SMEM_QKV (SA_BYTES + SB_BYTES)    // 55296
#define TOT0_4 4194304u                   // head-0 plane in float4
#define SLICE0 10923u                     // ceil(TOT0_4 / 384)

__global__ __launch_bounds__(256, 2)
void qkv_mma_kernel(const float* __restrict__ bq, const float* __restrict__ bk,
                    const float* __restrict__ bv, float* __restrict__ attn) {
    extern __shared__ char dyn[];
    bf16 (*sA)[2][64][24]  = (bf16(*)[2][64][24])dyn;
    bf16 (*sB)[2][128][24] = (bf16(*)[2][128][24])(dyn + SA_BYTES);

    const int tid  = threadIdx.x;
    const int wid  = tid >> 5;
    const int lane = tid & 31;
    const int wm = wid & 3;
    const int wn = wid >> 2;
    const int r0 = blockIdx.x * 64;
    const int n0 = blockIdx.y * 128;
    const unsigned bid = blockIdx.y * 64 + blockIdx.x;

    const int arow = tid >> 2, ahl = (tid >> 1) & 1, ahf = tid & 1;
    const bf16* srcA  = (ahl ? g_xl : g_xh) + (r0 + arow) * F + ahf * 8;
    const bf16* srcB0 = (ahl ? g_Wl : g_Wh) + (n0 + arow) * F + ahf * 8;
    const bf16* srcB1 = srcB0 + 64 * F;

    const int rA = (lane & 7) + ((lane >> 3) & 1) * 8;
    const int cA = (lane & 16) ? 8 : 0;
    const int rB = (lane & 7) + ((lane & 16) ? 8 : 0);
    const int cB = (lane & 8) ? 8 : 0;

    const unsigned zs = bid * SLICE0;
    const unsigned ze = (zs + SLICE0 < TOT0_4) ? zs + SLICE0 : TOT0_4;
    float* __restrict__ zp = attn;

    float acc[8][4] = {};

#pragma unroll
    for (int p = 0; p < 2; p++) {
        cp16(&sA[p][ahl][arow][ahf * 8], srcA + p * 16);
        cp16(&sB[p][ahl][arow][ahf * 8], srcB0 + p * 16);
        cp16(&sB[p][ahl][64 + arow][ahf * 8], srcB1 + p * 16);
        asm volatile("cp.async.commit_group;");
    }

    for (int kt = 0; kt < 16; kt++) {
        const int s = kt % 3;
        if (kt < 15) asm volatile("cp.async.wait_group 1;");
        else         asm volatile("cp.async.wait_group 0;");
        __syncthreads();

        if (kt + 2 < 16) {
            const int sn = (kt + 2) % 3;
            cp16(&sA[sn][ahl][arow][ahf * 8], srcA + (kt + 2) * 16);
            cp16(&sB[sn][ahl][arow][ahf * 8], srcB0 + (kt + 2) * 16);
            cp16(&sB[sn][ahl][64 + arow][ahf * 8], srcB1 + (kt + 2) * 16);
            asm volatile("cp.async.commit_group;");
        }
#pragma unroll
        for (int t = 0; t < 3; t++) {
            unsigned idx = zs + (unsigned)(kt * 3 + t) * 256u + (unsigned)tid;
            if (idx < ze) stg_cs_zero4(zp + idx * 4);
        }

        unsigned ah[4], al[4];
        ldm4(ah, &sA[s][0][wm * 16 + rA][cA]);
        ldm4(al, &sA[s][1][wm * 16 + rA][cA]);
#pragma unroll
        for (int ng = 0; ng < 4; ng++) {
            unsigned bh[4], bl[4];
            ldm4(bh, &sB[s][0][wn * 64 + ng * 16 + rB][cB]);
            ldm4(bl, &sB[s][1][wn * 64 + ng * 16 + rB][cB]);
            mma16816(acc[ng * 2 + 0], ah, bh + 0);
            mma16816(acc[ng * 2 + 0], al, bh + 0);
            mma16816(acc[ng * 2 + 0], ah, bl + 0);
            mma16816(acc[ng * 2 + 1], ah, bh + 2);
            mma16816(acc[ng * 2 + 1], al, bh + 2);
            mma16816(acc[ng * 2 + 1], ah, bl + 2);
        }
    }

    const int g  = lane >> 2;
    const int t2 = (lane & 3) * 2;
    const int matId = blockIdx.y >> 1;
    const float* bias = matId == 0 ? bq : matId == 1 ? bk : bv;
    float* dst = matId == 0 ? g_Q : matId == 1 ? g_K : g_V;
    const int ncol0 = (blockIdx.y & 1) * 128 + wn * 64;
    const int r = r0 + wm * 16 + g;
#pragma unroll
    for (int nt = 0; nt < 8; nt++) {
        int c = ncol0 + nt * 8 + t2;
        float b0 = bias[c], b1 = bias[c + 1];
        *(float2*)&dst[r * F + c]       = make_float2(acc[nt][0] + b0, acc[nt][1] + b1);
        *(float2*)&dst[(r + 8) * F + c] = make_float2(acc[nt][2] + b0, acc[nt][3] + b1);
    }
}

// ---------------------------------------------------------------------------
// Fused sparse attention + heads-1..3 zeroing (interleaved st.cs) + residual
// + LayerNorm. One block (128 threads = 4 warps) per row; warp w owns head w.
// Score phase: lane-per-neighbor full dot products (no shuffles).
// ---------------------------------------------------------------------------
__device__ __forceinline__ void zero_chunk(float* __restrict__ attn, int row,
                                           int tid, int c0) {
#pragma unroll
    for (int i = 0; i < 8; i++) {
        int idx = (c0 + i) * 128 + tid;          // [0, 3072)
        int h = 1 + (idx >> 10);
        int c4 = idx & 1023;
        stg_cs_zero4(attn + ((size_t)h * N_NODES + row) * N_NODES + c4 * 4);
    }
}

__global__ __launch_bounds__(128, 8)
void attn_kernel(const float* __restrict__ x,
                 const float* __restrict__ ln_g, const float* __restrict__ ln_b,
                 float* __restrict__ out, float* __restrict__ attn) {
    const int row  = blockIdx.x;
    const int tid  = threadIdx.x;
    const int w    = tid >> 5;
    const int lane = tid & 31;

    __shared__ int   s_nbr[MAXN];
    __shared__ float s_scores[H][MAXN];
    __shared__ float s_q[F];
    __shared__ float s_y[F];
    __shared__ int   s_warpcnt[4];
    __shared__ int   s_cnt;
    __shared__ float s_red[8];

    zero_chunk(attn, row, tid, 0);               // zeros chunk 1/3

    s_q[tid]       = g_Q[row * F + tid];
    s_q[tid + 128] = g_Q[row * F + tid + 128];

    // neighbor extraction from bitmap (deterministic, sorted)
    unsigned word = g_adj[row * WPR + tid];
    int c = __popc(word);
    int sc = c;
#pragma unroll
    for (int d = 1; d < 32; d <<= 1) {
        int v = __shfl_up_sync(0xffffffffu, sc, d);
        if (lane >= d) sc += v;
    }
    if (lane == 31) s_warpcnt[w] = sc;
    __syncthreads();

    int base = 0;
#pragma unroll
    for (int i = 0; i < 4; i++)
        if (i < w) base += s_warpcnt[i];
    int off = base + sc - c;
    unsigned ww = word;
    while (ww) {
        int b = __ffs(ww) - 1;
        ww &= ww - 1;
        if (off < MAXN) s_nbr[off] = (tid << 5) + b;
        off++;
    }
    if (tid == 127) s_cnt = base + sc;

    zero_chunk(attn, row, tid, 8);               // zeros chunk 2/3
    __syncthreads();

    int cnt = s_cnt;
    if (cnt > MAXN) cnt = MAXN;

    // ---- scores: lane t owns neighbor t (full 64-dim dot, no shuffles) ----
    const float invsqrt = 0.125f;  // 1/sqrt(64)
    const float4* __restrict__ sq4 = (const float4*)(s_q + w * HD);  // 16 float4
    for (int t = lane; t < cnt; t += 32) {
        const float4* __restrict__ krow = (const float4*)(g_K + s_nbr[t] * F + w * HD);
        float s0 = 0.f, s1 = 0.f, s2 = 0.f, s3 = 0.f;
#pragma unroll
        for (int cc = 0; cc < 4; cc++) {
            float4 q0 = sq4[cc * 4 + 0], k0 = krow[cc * 4 + 0];
            s0 += q0.x * k0.x + q0.y * k0.y + q0.z * k0.z + q0.w * k0.w;
            float4 q1 = sq4[cc * 4 + 1], k1 = krow[cc * 4 + 1];
            s1 += q1.x * k1.x + q1.y * k1.y + q1.z * k1.z + q1.w * k1.w;
            float4 q2 = sq4[cc * 4 + 2], k2 = krow[cc * 4 + 2];
            s2 += q2.x * k2.x + q2.y * k2.y + q2.z * k2.z + q2.w * k2.w;
            float4 q3 = sq4[cc * 4 + 3], k3 = krow[cc * 4 + 3];
            s3 += q3.x * k3.x + q3.y * k3.y + q3.z * k3.z + q3.w * k3.w;
        }
        s_scores[w][t] = ((s0 + s1) + (s2 + s3)) * invsqrt;
    }

    zero_chunk(attn, row, tid, 16);              // zeros chunk 3/3
    __syncthreads();   // zeros visible before scatter (block-scope W->W order)

    // ---- softmax over neighbors (per warp/head) ----
    float mx = -INFINITY;
    for (int t = lane; t < cnt; t += 32) mx = fmaxf(mx, s_scores[w][t]);
#pragma unroll
    for (int d = 16; d; d >>= 1) mx = fmaxf(mx, __shfl_xor_sync(0xffffffffu, mx, d));
    float sum = 0.0f;
    for (int t = lane; t < cnt; t += 32) {
        float e = expf(s_scores[w][t] - mx);
        s_scores[w][t] = e;
        sum += e;
    }
#pragma unroll
    for (int d = 16; d; d >>= 1) sum += __shfl_xor_sync(0xffffffffu, sum, d);
    float inv = 1.0f / sum;

    // scatter probabilities (head-0 zeros by GEMM kernel, h1-3 by this block)
    for (int t = lane; t < cnt; t += 32) {
        float p = s_scores[w][t] * inv;
        s_scores[w][t] = p;
        stg_cs_f32(attn + (size_t)w * N_NODES * N_NODES +
                   (size_t)row * N_NODES + s_nbr[t], p);
    }
    __syncwarp();

    // ---- AV with 4 independent accumulators ----
    const float* __restrict__ Vbase = g_V + w * HD + lane * 2;
    float2 a0 = make_float2(0.f, 0.f), a1 = make_float2(0.f, 0.f);
    float2 a2 = make_float2(0.f, 0.f), a3 = make_float2(0.f, 0.f);
    int j = 0;
    for (; j + 4 <= cnt; j += 4) {
        float p0 = s_scores[w][j],     p1 = s_scores[w][j + 1];
        float p2 = s_scores[w][j + 2], p3 = s_scores[w][j + 3];
        float2 v0 = *(const float2*)(Vbase + s_nbr[j] * F);
        float2 v1 = *(const float2*)(Vbase + s_nbr[j + 1] * F);
        float2 v2 = *(const float2*)(Vbase + s_nbr[j + 2] * F);
        float2 v3 = *(const float2*)(Vbase + s_nbr[j + 3] * F);
        a0.x += p0 * v0.x; a0.y += p0 * v0.y;
        a1.x += p1 * v1.x; a1.y += p1 * v1.y;
        a2.x += p2 * v2.x; a2.y += p2 * v2.y;
        a3.x += p3 * v3.x; a3.y += p3 * v3.y;
    }
    for (; j < cnt; j++) {
        float p = s_scores[w][j];
        float2 v = *(const float2*)(Vbase + s_nbr[j] * F);
        a0.x += p * v.x; a0.y += p * v.y;
    }
    float2 acc;
    acc.x = (a0.x + a1.x) + (a2.x + a3.x);
    acc.y = (a0.y + a1.y) + (a2.y + a3.y);
    s_y[w * HD + lane * 2]     = acc.x;
    s_y[w * HD + lane * 2 + 1] = acc.y;
    __syncthreads();

    // ---- residual + LayerNorm ----
    float y0 = s_y[tid * 2]     + x[row * F + tid * 2];
    float y1 = s_y[tid * 2 + 1] + x[row * F + tid * 2 + 1];
    float ps = y0 + y1;
    float pq = y0 * y0 + y1 * y1;
#pragma unroll
    for (int d = 16; d; d >>= 1) {
        ps += __shfl_xor_sync(0xffffffffu, ps, d);
        pq += __shfl_xor_sync(0xffffffffu, pq, d);
    }
    if (lane == 0) { s_red[w] = ps; s_red[4 + w] = pq; }
    __syncthreads();
    float tot  = s_red[0] + s_red[1] + s_red[2] + s_red[3];
    float totq = s_red[4] + s_red[5] + s_red[6] + s_red[7];
    float mu  = tot * (1.0f / 256.0f);
    float var = totq * (1.0f / 256.0f) - mu * mu;
    float rs  = rsqrtf(var + 1e-5f);
    out[row * F + tid * 2]     = (y0 - mu) * rs * ln_g[tid * 2]     + ln_b[tid * 2];
    out[row * F + tid * 2 + 1] = (y1 - mu) * rs * ln_g[tid * 2 + 1] + ln_b[tid * 2 + 1];
}

// ---------------------------------------------------------------------------
extern "C" void kernel_launch(void* const* d_in, const int* in_sizes, int n_in,
                              void* d_out, int out_size) {
    const float* x  = (const float*)d_in[0];
    const int*   ei = (const int*)d_in[1];
    const float* Wq = (const float*)d_in[2];
    const float* bq = (const float*)d_in[3];
    const float* Wk = (const float*)d_in[4];
    const float* bk = (const float*)d_in[5];
    const float* Wv = (const float*)d_in[6];
    const float* bv = (const float*)d_in[7];
    const float* lg = (const float*)d_in[8];
    const float* lb = (const float*)d_in[9];

    const int E = in_sizes[1] / 2;

    float* out  = (float*)d_out;                 // [1, 4096, 256]
    float* attn = out + (size_t)N_NODES * F;     // [1, 4, 4096, 4096]

    convert_kernel<<<(NX + NW + NADJ + 255) / 256, 256>>>(x, Wq, Wk, Wv);
    scatter_edges_kernel<<<(E + 255) / 256, 256>>>(ei, E);

    cudaFuncSetAttribute(qkv_mma_kernel,
                         cudaFuncAttributeMaxDynamicSharedMemorySize, SMEM_QKV);
    dim3 gg(64, 6);
    qkv_mma_kernel<<<gg, 256, SMEM_QKV>>>(bq, bk, bv, attn);

    attn_kernel<<<N_NODES, 128>>>(x, lg, lb, out, attn);
}

// round 10
// speedup vs baseline: 1.2719x; 1.2719x over previous
#include <cuda_runtime.h>
#include <cuda_bf16.h>
#include <math.h>
#include <stdint.h>

#define N_NODES 4096
#define F 256
#define H 4
#define HD 64
#define WPR (N_NODES / 32)
#define MAXN 256

typedef __nv_bfloat16 bf16;

// ---- scratch (static device arrays; no allocations allowed) ----
__device__ float g_Q[N_NODES * F];
__device__ float g_K[N_NODES * F];
__device__ float g_V[N_NODES * F];
__device__ unsigned g_adj[N_NODES * WPR];
__device__ bf16 g_xh[N_NODES * F];
__device__ bf16 g_xl[N_NODES * F];
__device__ bf16 g_Wh[3 * F * F];
__device__ bf16 g_Wl[3 * F * F];

// ---------------------------------------------------------------------------
// PTX helpers (round-8 proven set)
// ---------------------------------------------------------------------------
__device__ __forceinline__ void cp16(void* dst, const void* src) {
    unsigned d = (unsigned)__cvta_generic_to_shared(dst);
    asm volatile("cp.async.cg.shared.global [%0], [%1], 16;" :: "r"(d), "l"(src));
}
__device__ __forceinline__ void ldm4(unsigned* r, const void* p) {
    unsigned a = (unsigned)__cvta_generic_to_shared(p);
    asm volatile("ldmatrix.sync.aligned.m8n8.x4.shared.b16 {%0,%1,%2,%3}, [%4];"
                 : "=r"(r[0]), "=r"(r[1]), "=r"(r[2]), "=r"(r[3]) : "r"(a));
}
__device__ __forceinline__ void mma16816(float* c, const unsigned* a, const unsigned* b) {
    asm volatile(
        "mma.sync.aligned.m16n8k16.row.col.f32.bf16.bf16.f32 "
        "{%0,%1,%2,%3}, {%4,%5,%6,%7}, {%8,%9}, {%0,%1,%2,%3};"
        : "+f"(c[0]), "+f"(c[1]), "+f"(c[2]), "+f"(c[3])
        : "r"(a[0]), "r"(a[1]), "r"(a[2]), "r"(a[3]), "r"(b[0]), "r"(b[1]));
}

// ---------------------------------------------------------------------------
// Prep: bf16 hi/lo split of x and [Wq;Wk;Wv] + adjacency bitmap clear (fused)
// ---------------------------------------------------------------------------
#define NX (N_NODES * F)
#define NW (3 * F * F)
#define NADJ (N_NODES * WPR)
__global__ void convert_kernel(const float* __restrict__ x,
                               const float* __restrict__ Wq,
                               const float* __restrict__ Wk,
                               const float* __restrict__ Wv) {
    int i = blockIdx.x * 256 + threadIdx.x;
    float v; bf16 *dh, *dl; int di;
    if (i < NX) { v = x[i]; dh = g_xh; dl = g_xl; di = i; }
    else if (i < NX + NW) {
        int j = i - NX;
        int mat = j >> 16; int e = j & 65535;
        v = (mat == 0 ? Wq : mat == 1 ? Wk : Wv)[e];
        dh = g_Wh; dl = g_Wl; di = j;
    } else {
        int j = i - NX - NW;
        if (j < NADJ) g_adj[j] = 0u;
        return;
    }
    bf16 h = __float2bfloat16(v);
    dh[di] = h;
    dl[di] = __float2bfloat16(v - __bfloat162float(h));
}

__global__ void scatter_edges_kernel(const int* __restrict__ ei, int E) {
    int i = blockIdx.x * blockDim.x + threadIdx.x;
    if (i >= E) return;
    int s = ei[i];
    int d = ei[E + i];
    atomicOr(&g_adj[s * WPR + (d >> 5)], 1u << (d & 31));
}

// ---------------------------------------------------------------------------
// Tensor-core QKV GEMM (bf16 hi/lo, 3-term) + heads 0-1 attn zeroing via STG.
// BM=64 BN=128, grid (64,6)=384 blocks, 256 thr = 8 warps, warp tile 16x64.
// 3-stage cp.async pipeline, one __syncthreads per k-step, 48B-stride smem.
// ---------------------------------------------------------------------------
#define SA_BYTES (3 * 2 * 64 * 24 * 2)    // 18432
#define SB_BYTES (3 * 2 * 128 * 24 * 2)   // 36864
#define SMEM_QKV (SA_BYTES + SB_BYTES)    // 55296
#define TOT01_4 8388608u                  // heads 0-1 planes in float4
#define SLICE01 21846u                    // ceil(TOT01_4 / 384)
#define ZPT 6                             // zero float4-stores / thread / k-iter

__global__ __launch_bounds__(256, 2)
void qkv_mma_kernel(const float* __restrict__ bq, const float* __restrict__ bk,
                    const float* __restrict__ bv, float* __restrict__ attn) {
    extern __shared__ char dyn[];
    bf16 (*sA)[2][64][24]  = (bf16(*)[2][64][24])dyn;
    bf16 (*sB)[2][128][24] = (bf16(*)[2][128][24])(dyn + SA_BYTES);

    const int tid  = threadIdx.x;
    const int wid  = tid >> 5;
    const int lane = tid & 31;
    const int wm = wid & 3;
    const int wn = wid >> 2;
    const int r0 = blockIdx.x * 64;
    const int n0 = blockIdx.y * 128;
    const unsigned bid = blockIdx.y * 64 + blockIdx.x;

    const int arow = tid >> 2, ahl = (tid >> 1) & 1, ahf = tid & 1;
    const bf16* srcA  = (ahl ? g_xl : g_xh) + (r0 + arow) * F + ahf * 8;
    const bf16* srcB0 = (ahl ? g_Wl : g_Wh) + (n0 + arow) * F + ahf * 8;
    const bf16* srcB1 = srcB0 + 64 * F;

    const int rA = (lane & 7) + ((lane >> 3) & 1) * 8;
    const int cA = (lane & 16) ? 8 : 0;
    const int rB = (lane & 7) + ((lane & 16) ? 8 : 0);
    const int cB = (lane & 8) ? 8 : 0;

    const unsigned zs = bid * SLICE01;
    const unsigned ze = (zs + SLICE01 < TOT01_4) ? zs + SLICE01 : TOT01_4;
    float4* __restrict__ zp = (float4*)attn;
    const float4 z4 = make_float4(0.f, 0.f, 0.f, 0.f);

    float acc[8][4] = {};

#pragma unroll
    for (int p = 0; p < 2; p++) {
        cp16(&sA[p][ahl][arow][ahf * 8], srcA + p * 16);
        cp16(&sB[p][ahl][arow][ahf * 8], srcB0 + p * 16);
        cp16(&sB[p][ahl][64 + arow][ahf * 8], srcB1 + p * 16);
        asm volatile("cp.async.commit_group;");
    }

    for (int kt = 0; kt < 16; kt++) {
        const int s = kt % 3;
        if (kt < 15) asm volatile("cp.async.wait_group 1;");
        else         asm volatile("cp.async.wait_group 0;");
        __syncthreads();

        if (kt + 2 < 16) {
            const int sn = (kt + 2) % 3;
            cp16(&sA[sn][ahl][arow][ahf * 8], srcA + (kt + 2) * 16);
            cp16(&sB[sn][ahl][arow][ahf * 8], srcB0 + (kt + 2) * 16);
            cp16(&sB[sn][ahl][64 + arow][ahf * 8], srcB1 + (kt + 2) * 16);
            asm volatile("cp.async.commit_group;");
        }
        // interleaved heads-0/1 zero-streaming (fire-and-forget)
#pragma unroll
        for (int t = 0; t < ZPT; t++) {
            unsigned idx = zs + (unsigned)(kt * ZPT + t) * 256u + (unsigned)tid;
            if (idx < ze) zp[idx] = z4;
        }

        unsigned ah[4], al[4];
        ldm4(ah, &sA[s][0][wm * 16 + rA][cA]);
        ldm4(al, &sA[s][1][wm * 16 + rA][cA]);
#pragma unroll
        for (int ng = 0; ng < 4; ng++) {
            unsigned bh[4], bl[4];
            ldm4(bh, &sB[s][0][wn * 64 + ng * 16 + rB][cB]);
            ldm4(bl, &sB[s][1][wn * 64 + ng * 16 + rB][cB]);
            mma16816(acc[ng * 2 + 0], ah, bh + 0);
            mma16816(acc[ng * 2 + 0], al, bh + 0);
            mma16816(acc[ng * 2 + 0], ah, bl + 0);
            mma16816(acc[ng * 2 + 1], ah, bh + 2);
            mma16816(acc[ng * 2 + 1], al, bh + 2);
            mma16816(acc[ng * 2 + 1], ah, bl + 2);
        }
    }

    const int g  = lane >> 2;
    const int t2 = (lane & 3) * 2;
    const int matId = blockIdx.y >> 1;
    const float* bias = matId == 0 ? bq : matId == 1 ? bk : bv;
    float* dst = matId == 0 ? g_Q : matId == 1 ? g_K : g_V;
    const int ncol0 = (blockIdx.y & 1) * 128 + wn * 64;
    const int r = r0 + wm * 16 + g;
#pragma unroll
    for (int nt = 0; nt < 8; nt++) {
        int c = ncol0 + nt * 8 + t2;
        float b0 = bias[c], b1 = bias[c + 1];
        *(float2*)&dst[r * F + c]       = make_float2(acc[nt][0] + b0, acc[nt][1] + b1);
        *(float2*)&dst[(r + 8) * F + c] = make_float2(acc[nt][2] + b0, acc[nt][3] + b1);
    }
}

// ---------------------------------------------------------------------------
// Fused sparse attention + heads-2/3 zeroing (STG, up-front) + residual + LN.
// One block (128 threads = 4 warps) per row; warp w owns head w.
// Scores: 8-lanes-per-neighbor (coalesced 128B row chunks), depth-3 shuffle
// reduction, 2 groups of 4 neighbors in flight.
// ---------------------------------------------------------------------------
__global__ __launch_bounds__(128, 8)
void attn_kernel(const float* __restrict__ x,
                 const float* __restrict__ ln_g, const float* __restrict__ ln_b,
                 float* __restrict__ out, float* __restrict__ attn) {
    const int row  = blockIdx.x;
    const int tid  = threadIdx.x;
    const int w    = tid >> 5;
    const int lane = tid & 31;

    // zero this row for heads 2..3 (heads 0-1 done by GEMM kernel)
    {
        const float4 z = make_float4(0.f, 0.f, 0.f, 0.f);
#pragma unroll
        for (int i = 0; i < 16; i++) {
            int idx = i * 128 + tid;              // [0, 2048)
            int h = 2 + (idx >> 10);
            int c4 = idx & 1023;
            ((float4*)(attn + ((size_t)h * N_NODES + row) * N_NODES))[c4] = z;
        }
    }

    __shared__ int   s_nbr[MAXN];
    __shared__ float s_scores[H][MAXN];
    __shared__ float s_q[F];
    __shared__ float s_y[F];
    __shared__ int   s_warpcnt[4];
    __shared__ int   s_cnt;
    __shared__ float s_red[8];

    s_q[tid]       = g_Q[row * F + tid];
    s_q[tid + 128] = g_Q[row * F + tid + 128];

    // neighbor extraction from bitmap (deterministic, sorted)
    unsigned word = g_adj[row * WPR + tid];
    int c = __popc(word);
    int sc = c;
#pragma unroll
    for (int d = 1; d < 32; d <<= 1) {
        int v = __shfl_up_sync(0xffffffffu, sc, d);
        if (lane >= d) sc += v;
    }
    if (lane == 31) s_warpcnt[w] = sc;
    __syncthreads();

    int base = 0;
#pragma unroll
    for (int i = 0; i < 4; i++)
        if (i < w) base += s_warpcnt[i];
    int off = base + sc - c;
    unsigned ww = word;
    while (ww) {
        int b = __ffs(ww) - 1;
        ww &= ww - 1;
        if (off < MAXN) s_nbr[off] = (tid << 5) + b;
        off++;
    }
    if (tid == 127) s_cnt = base + sc;
    __syncthreads();

    int cnt = s_cnt;
    if (cnt > MAXN) cnt = MAXN;

    // ---- scores: 8 lanes per neighbor, 8 neighbors in flight ----
    // lane = g8*8 + l8: group g8 (0..3) owns neighbor slots bb+g8 / bb+4+g8;
    // lane l8 covers floats [4*l8, 4*l8+4) and [32+4*l8, 32+4*l8+4).
    const float invsqrt = 0.125f;  // 1/sqrt(64)
    const int g8 = lane >> 3;
    const int l8 = lane & 7;
    const float4* __restrict__ sq4 = (const float4*)(s_q + w * HD);
    float4 q0 = sq4[l8];
    float4 q1 = sq4[8 + l8];
    for (int bb = 0; bb < cnt; bb += 8) {
        int t0 = bb + g8;
        int t1 = bb + 4 + g8;
        int m0 = s_nbr[t0 < cnt ? t0 : 0];
        int m1 = s_nbr[t1 < cnt ? t1 : 0];
        const float4* k0p = (const float4*)(g_K + m0 * F + w * HD);
        const float4* k1p = (const float4*)(g_K + m1 * F + w * HD);
        float4 a0 = k0p[l8], a1 = k0p[8 + l8];
        float4 b0 = k1p[l8], b1 = k1p[8 + l8];
        float p0 = q0.x * a0.x + q0.y * a0.y + q0.z * a0.z + q0.w * a0.w
                 + q1.x * a1.x + q1.y * a1.y + q1.z * a1.z + q1.w * a1.w;
        float p1 = q0.x * b0.x + q0.y * b0.y + q0.z * b0.z + q0.w * b0.w
                 + q1.x * b1.x + q1.y * b1.y + q1.z * b1.z + q1.w * b1.w;
#pragma unroll
        for (int d = 4; d; d >>= 1) {
            p0 += __shfl_xor_sync(0xffffffffu, p0, d);
            p1 += __shfl_xor_sync(0xffffffffu, p1, d);
        }
        if (l8 == 0) {
            if (t0 < cnt) s_scores[w][t0] = p0 * invsqrt;
            if (t1 < cnt) s_scores[w][t1] = p1 * invsqrt;
        }
    }
    __syncwarp();

    // ---- softmax over neighbors (per warp/head) ----
    float mx = -INFINITY;
    for (int t = lane; t < cnt; t += 32) mx = fmaxf(mx, s_scores[w][t]);
#pragma unroll
    for (int d = 16; d; d >>= 1) mx = fmaxf(mx, __shfl_xor_sync(0xffffffffu, mx, d));
    float sum = 0.0f;
    for (int t = lane; t < cnt; t += 32) {
        float e = expf(s_scores[w][t] - mx);
        s_scores[w][t] = e;
        sum += e;
    }
#pragma unroll
    for (int d = 16; d; d >>= 1) sum += __shfl_xor_sync(0xffffffffu, sum, d);
    float inv = 1.0f / sum;

    // scatter probabilities (heads 0-1 zeros by GEMM kernel, 2-3 by this block;
    // block-entry zeros are ordered before this store by the barriers above)
    for (int t = lane; t < cnt; t += 32) {
        float p = s_scores[w][t] * inv;
        s_scores[w][t] = p;
        attn[(size_t)w * N_NODES * N_NODES + (size_t)row * N_NODES + s_nbr[t]] = p;
    }
    __syncwarp();

    // ---- AV with 4 independent accumulators ----
    const float* __restrict__ Vbase = g_V + w * HD + lane * 2;
    float2 a0 = make_float2(0.f, 0.f), a1 = make_float2(0.f, 0.f);
    float2 a2 = make_float2(0.f, 0.f), a3 = make_float2(0.f, 0.f);
    int j = 0;
    for (; j + 4 <= cnt; j += 4) {
        float p0 = s_scores[w][j],     p1 = s_scores[w][j + 1];
        float p2 = s_scores[w][j + 2], p3 = s_scores[w][j + 3];
        float2 v0 = *(const float2*)(Vbase + s_nbr[j] * F);
        float2 v1 = *(const float2*)(Vbase + s_nbr[j + 1] * F);
        float2 v2 = *(const float2*)(Vbase + s_nbr[j + 2] * F);
        float2 v3 = *(const float2*)(Vbase + s_nbr[j + 3] * F);
        a0.x += p0 * v0.x; a0.y += p0 * v0.y;
        a1.x += p1 * v1.x; a1.y += p1 * v1.y;
        a2.x += p2 * v2.x; a2.y += p2 * v2.y;
        a3.x += p3 * v3.x; a3.y += p3 * v3.y;
    }
    for (; j < cnt; j++) {
        float p = s_scores[w][j];
        float2 v = *(const float2*)(Vbase + s_nbr[j] * F);
        a0.x += p * v.x; a0.y += p * v.y;
    }
    float2 acc;
    acc.x = (a0.x + a1.x) + (a2.x + a3.x);
    acc.y = (a0.y + a1.y) + (a2.y + a3.y);
    s_y[w * HD + lane * 2]     = acc.x;
    s_y[w * HD + lane * 2 + 1] = acc.y;
    __syncthreads();

    // ---- residual + LayerNorm ----
    float y0 = s_y[tid * 2]     + x[row * F + tid * 2];
    float y1 = s_y[tid * 2 + 1] + x[row * F + tid * 2 + 1];
    float ps = y0 + y1;
    float pq = y0 * y0 + y1 * y1;
#pragma unroll
    for (int d = 16; d; d >>= 1) {
        ps += __shfl_xor_sync(0xffffffffu, ps, d);
        pq += __shfl_xor_sync(0xffffffffu, pq, d);
    }
    if (lane == 0) { s_red[w] = ps; s_red[4 + w] = pq; }
    __syncthreads();
    float tot  = s_red[0] + s_red[1] + s_red[2] + s_red[3];
    float totq = s_red[4] + s_red[5] + s_red[6] + s_red[7];
    float mu  = tot * (1.0f / 256.0f);
    float var = totq * (1.0f / 256.0f) - mu * mu;
    float rs  = rsqrtf(var + 1e-5f);
    out[row * F + tid * 2]     = (y0 - mu) * rs * ln_g[tid * 2]     + ln_b[tid * 2];
    out[row * F + tid * 2 + 1] = (y1 - mu) * rs * ln_g[tid * 2 + 1] + ln_b[tid * 2 + 1];
}

// ---------------------------------------------------------------------------
extern "C" void kernel_launch(void* const* d_in, const int* in_sizes, int n_in,
                              void* d_out, int out_size) {
    const float* x  = (const float*)d_in[0];
    const int*   ei = (const int*)d_in[1];
    const float* Wq = (const float*)d_in[2];
    const float* bq = (const float*)d_in[3];
    const float* Wk = (const float*)d_in[4];
    const float* bk = (const float*)d_in[5];
    const float* Wv = (const float*)d_in[6];
    const float* bv = (const float*)d_in[7];
    const float* lg = (const float*)d_in[8];
    const float* lb = (const float*)d_in[9];

    const int E = in_sizes[1] / 2;

    float* out  = (float*)d_out;                 // [1, 4096, 256]
    float* attn = out + (size_t)N_NODES * F;     // [1, 4, 4096, 4096]

    convert_kernel<<<(NX + NW + NADJ + 255) / 256, 256>>>(x, Wq, Wk, Wv);
    scatter_edges_kernel<<<(E + 255) / 256, 256>>>(ei, E);

    cudaFuncSetAttribute(qkv_mma_kernel,
                         cudaFuncAttributeMaxDynamicSharedMemorySize, SMEM_QKV);
    dim3 gg(64, 6);
    qkv_mma_kernel<<<gg, 256, SMEM_QKV>>>(bq, bk, bv, attn);

    attn_kernel<<<N_NODES, 128>>>(x, lg, lb, out, attn);
}